// round 16
// baseline (speedup 1.0000x reference)
#include <cuda_runtime.h>
#include <cuda_fp16.h>
#include <math_constants.h>
#include <cstdint>

// Problem constants
#define Bv   4
#define Tv   2048
#define Cv   1024
#define Hv   16
#define HDv  64
#define NTOK (Bv * Tv)      // 8192
#define C3   (3 * Cv)       // 3072

// ---- Scratch (static device globals -- allocation-guard safe) -------------
__device__ __align__(16) unsigned short gx16[(size_t)NTOK * Cv];      // x [M,K]
__device__ __align__(16) unsigned short gatt16[(size_t)NTOK * Cv];    // att [M,K]
__device__ __align__(16) unsigned short gw1t16[(size_t)C3 * Cv];      // w_qkv^T [N,K]
__device__ __align__(16) unsigned short gw2t16[(size_t)Cv * Cv];      // w_proj^T [N,K]
__device__ __align__(16) unsigned short gq16[(size_t)Bv * Hv * Tv * HDv];  // [bh][t][d] (pre-scaled)
__device__ __align__(16) unsigned short gk16[(size_t)Bv * Hv * Tv * HDv];  // [bh][t][d]
__device__ __align__(16) unsigned short gv16[(size_t)Bv * Hv * Tv * HDv];  // [bh][t][d] (unified!)

// scale folded into q: 1/sqrt(64) * log2(e)
#define QSCALE 0.1803368801111204f

// ---- portable tensor-core helpers (sm_80+ PTX, compiles at compute_103) ---
__device__ __forceinline__ uint32_t smem_u32(const void* p) {
    uint32_t a;
    asm("{ .reg .u64 t; cvta.to.shared.u64 t, %1; cvt.u32.u64 %0, t; }"
        : "=r"(a) : "l"(p));
    return a;
}
__device__ __forceinline__ void ldsm_x4(uint32_t a, uint32_t& r0, uint32_t& r1,
                                        uint32_t& r2, uint32_t& r3) {
    asm volatile("ldmatrix.sync.aligned.m8n8.x4.shared.b16 {%0,%1,%2,%3}, [%4];"
                 : "=r"(r0), "=r"(r1), "=r"(r2), "=r"(r3) : "r"(a));
}
__device__ __forceinline__ void ldsm_x4_t(uint32_t a, uint32_t& r0, uint32_t& r1,
                                          uint32_t& r2, uint32_t& r3) {
    asm volatile("ldmatrix.sync.aligned.m8n8.x4.trans.shared.b16 {%0,%1,%2,%3}, [%4];"
                 : "=r"(r0), "=r"(r1), "=r"(r2), "=r"(r3) : "r"(a));
}
__device__ __forceinline__ void mma16816(float* d, const uint32_t* a, const uint32_t* b) {
    asm volatile("mma.sync.aligned.m16n8k16.row.col.f32.f16.f16.f32 "
                 "{%0,%1,%2,%3}, {%4,%5,%6,%7}, {%8,%9}, {%0,%1,%2,%3};"
                 : "+f"(d[0]), "+f"(d[1]), "+f"(d[2]), "+f"(d[3])
                 : "r"(a[0]), "r"(a[1]), "r"(a[2]), "r"(a[3]),
                   "r"(b[0]), "r"(b[1]));
}
__device__ __forceinline__ void cp16(uint32_t s, const unsigned short* g) {
    asm volatile("cp.async.cg.shared.global [%0], [%1], 16;"
                 :: "r"(s), "l"(__cvta_generic_to_global(g)) : "memory");
}
__device__ __forceinline__ void cp_commit() {
    asm volatile("cp.async.commit_group;" ::: "memory");
}
template <int N> __device__ __forceinline__ void cp_wait() {
    asm volatile("cp.async.wait_group %0;" :: "n"(N) : "memory");
}
// pack two fp32 into fp16x2: a -> low half, b -> high half (RN)
__device__ __forceinline__ uint32_t pack_h2(float a, float b) {
    uint32_t r;
    asm("cvt.rn.f16x2.f32 %0, %2, %1;" : "=r"(r) : "f"(a), "f"(b));
    return r;
}
__device__ __forceinline__ float ex2f(float x) {
    float r; asm("ex2.approx.f32 %0, %1;" : "=f"(r) : "f"(x)); return r;
}

// ---------------------------------------------------------------------------
// x fp32 -> fp16
// ---------------------------------------------------------------------------
__global__ __launch_bounds__(256)
void convert_x(const float* __restrict__ xin)
{
    const size_t i = (size_t)blockIdx.x * 256 + threadIdx.x;   // float4 index
    const float4 v = ((const float4*)xin)[i];
    uint2 o;
    o.x = pack_h2(v.x, v.y);
    o.y = pack_h2(v.z, v.w);
    ((uint2*)gx16)[i] = o;
}

// ---------------------------------------------------------------------------
// Weight transpose: w [K,N] fp32 -> wT fp16 [N,K]
// ---------------------------------------------------------------------------
__global__ __launch_bounds__(256)
void transpose_h(const float* __restrict__ in, int mode)
{
    const int N = mode == 0 ? C3 : Cv;
    unsigned short* dst = mode == 0 ? gw1t16 : gw2t16;
    __shared__ float t[32][33];
    const int tx = threadIdx.x, ty = threadIdx.y;
    const int x  = blockIdx.x * 32 + tx;     // N index (read)
    const int y0 = blockIdx.y * 32;          // K base
    #pragma unroll
    for (int j = 0; j < 4; ++j)
        t[ty + 8 * j][tx] = in[(size_t)(y0 + ty + 8 * j) * N + x];
    __syncthreads();
    const int ox  = y0 + tx;                 // K index (write)
    const int oy0 = blockIdx.x * 32;         // N base (write)
    #pragma unroll
    for (int j = 0; j < 4; ++j) {
        const float v = t[tx][ty + 8 * j];
        dst[(size_t)(oy0 + ty + 8 * j) * Cv + ox] =
            __half_as_ushort(__float2half_rn(v));
    }
}

// ---------------------------------------------------------------------------
// fp16 tensor-core GEMM via mma.sync: C[M,N] = A[M,1024] @ B[N,1024]^T,
// fp32 reg accumulators. 128x128 tile, BK=64, 8 warps (4M x 2N).
// Persistent CTAs (grid=296), 3-stage cp.async pipeline, fragment
// double-buffering across ks (LDSM for ks+1 overlaps MMA of ks), next-tile
// staging issued before the epilogue (stores overlap loads).
// MODE 0: A=gx16,  B=gw1t16, scatter fp16 into gq16 (scaled)/gk16/gv16 [t][d]
// MODE 1: A=gatt16, B=gw2t16, write Cout fp32 row-major (N=1024)
// ---------------------------------------------------------------------------
#define TP2     144                        // 64 fp16 = 128B + 16 pad
#define TB2     (128 * TP2)                // 18432 per tensor tile
#define STAGE2  (2 * TB2)                  // A + B = 36864
#define GEMM_SMEM_BYTES (3 * STAGE2)       // 110592
#define GEMM_GRID 296                      // 2 CTAs x 148 SMs

template <int MODE>
__global__ __launch_bounds__(256, 2)
void mma_gemm(float* __restrict__ Cout)
{
    extern __shared__ char smem[];
    const uint32_t sbase = smem_u32(smem);

    const int tid  = threadIdx.x;
    const int lane = tid & 31;
    const int wid  = tid >> 5;
    const int wm   = wid & 3;
    const int wn   = wid >> 2;
    const int lr   = lane & 7;
    const int sub  = lane >> 3;

    const unsigned short* A16 = (MODE == 0) ? gx16   : gatt16;
    const unsigned short* B16 = (MODE == 0) ? gw1t16 : gw2t16;
    const int NT_N   = (MODE == 0) ? (C3 / 128) : (Cv / 128);
    const int NTILES = NT_N * (NTOK / 128);

    const uint32_t aOff = (uint32_t)((wm * 32 + (sub & 1) * 8 + lr) * TP2
                                     + (sub >> 1) * 16);
    const uint32_t bOff = (uint32_t)((wn * 64 + (sub >> 1) * 8 + lr) * TP2
                                     + (sub & 1) * 16);

    auto stage_chunk = [&](int sm0, int sn0, int kc, uint32_t sb) {
        #pragma unroll
        for (int i = 0; i < 8; ++i) {
            const int f   = tid + (i << 8);
            const int ten = f >> 10;               // 0:A 1:B
            const int g   = f & 1023;
            const int row = g >> 3, cb = (g & 7) << 4;
            const unsigned short* src = (ten ? B16 + (size_t)(sn0 + row) * Cv
                                             : A16 + (size_t)(sm0 + row) * Cv)
                                        + kc + (cb >> 1);
            cp16(sb + (uint32_t)ten * TB2 + row * TP2 + cb, src);
        }
        cp_commit();
    };

    int tile = blockIdx.x;
    int m0 = (tile / NT_N) * 128;
    int n0 = (tile % NT_N) * 128;
    stage_chunk(m0, n0, 0, sbase);
    stage_chunk(m0, n0, 64, sbase + STAGE2);

    while (true) {
        float d[2][8][4] = {};
        uint32_t aF[2][2][4], bF[2][8][2];

        auto load_frags = [&](uint32_t sb, int ks, int buf) {
            const uint32_t ko = (uint32_t)ks * 32;
            #pragma unroll
            for (int mt = 0; mt < 2; ++mt)
                ldsm_x4(sb + aOff + mt * (16 * TP2) + ko,
                        aF[buf][mt][0], aF[buf][mt][1],
                        aF[buf][mt][2], aF[buf][mt][3]);
            #pragma unroll
            for (int p = 0; p < 4; ++p) {
                uint32_t x0, x1, x2, x3;
                ldsm_x4(sb + TB2 + bOff + p * (16 * TP2) + ko, x0, x1, x2, x3);
                bF[buf][2 * p][0] = x0;     bF[buf][2 * p][1] = x1;
                bF[buf][2 * p + 1][0] = x2; bF[buf][2 * p + 1][1] = x3;
            }
        };

        #pragma unroll 1
        for (int chunk = 0; chunk < 16; ++chunk) {
            if (chunk < 15) cp_wait<1>(); else cp_wait<0>();
            __syncthreads();
            if (chunk + 2 < 16)
                stage_chunk(m0, n0, (chunk + 2) << 6,
                            sbase + (uint32_t)((chunk + 2) % 3) * STAGE2);

            const uint32_t sb = sbase + (uint32_t)(chunk % 3) * STAGE2;
            load_frags(sb, 0, 0);
            #pragma unroll
            for (int ks = 0; ks < 4; ++ks) {
                const int cur = ks & 1;
                if (ks < 3) load_frags(sb, ks + 1, cur ^ 1);
                #pragma unroll
                for (int mt = 0; mt < 2; ++mt)
                    #pragma unroll
                    for (int nt = 0; nt < 8; ++nt)
                        mma16816(d[mt][nt], aF[cur][mt], bF[cur][nt]);
            }
        }

        const int next = tile + (int)gridDim.x;
        __syncthreads();                 // all MMA smem reads complete
        if (next < NTILES) {             // overlap next prologue w/ epilogue
            const int nm0 = (next / NT_N) * 128;
            const int nn0 = (next % NT_N) * 128;
            stage_chunk(nm0, nn0, 0, sbase);
            stage_chunk(nm0, nn0, 64, sbase + STAGE2);
        }

        // Epilogue (current tile)
        #pragma unroll
        for (int mt = 0; mt < 2; ++mt) {
            const int mA = m0 + wm * 32 + mt * 16 + (lane >> 2);
            if (MODE == 0) {
                const int bb = mA >> 11;
                const int tt = mA & 2047;
                const int t2 = (mA + 8) & 2047;   // same batch (128 | 2048)
                #pragma unroll
                for (int nt = 0; nt < 8; ++nt) {
                    const int ncol = n0 + wn * 64 + nt * 8 + (lane & 3) * 2;
                    const int sec = ncol >> 10;          // 0:q 1:k 2:v
                    const int hh  = (ncol & 1023) >> 6;
                    const int dd  = ncol & 63;
                    const float qs = (sec == 0) ? QSCALE : 1.0f;
                    const uint32_t p0 = pack_h2(d[mt][nt][0] * qs, d[mt][nt][1] * qs);
                    const uint32_t p1 = pack_h2(d[mt][nt][2] * qs, d[mt][nt][3] * qs);
                    unsigned short* dh = (sec == 0) ? gq16
                                       : (sec == 1) ? gk16 : gv16;
                    const size_t base = (size_t)(bb * Hv + hh) * Tv;
                    *(uint32_t*)(dh + (base + tt) * 64 + dd) = p0;
                    *(uint32_t*)(dh + (base + t2) * 64 + dd) = p1;
                }
            } else {
                #pragma unroll
                for (int nt = 0; nt < 8; ++nt) {
                    const int ncol = n0 + wn * 64 + nt * 8 + (lane & 3) * 2;
                    *(float2*)(Cout + (size_t)mA * Cv + ncol) =
                        make_float2(d[mt][nt][0], d[mt][nt][1]);
                    *(float2*)(Cout + (size_t)(mA + 8) * Cv + ncol) =
                        make_float2(d[mt][nt][2], d[mt][nt][3]);
                }
            }
        }

        if (next >= NTILES) break;
        tile = next;
        m0 = (tile / NT_N) * 128;
        n0 = (tile % NT_N) * 128;
    }
}

// ---------------------------------------------------------------------------
// fp16 tensor-core causal flash attention (mma.sync), bounded-score softmax.
// V now stored [bh][t][d] like K (coalesced GEMM epilogue); PV B-fragments
// come from ldmatrix.x4.trans of the [t][d] tile. Row-sum l via ones-MMA.
// ---------------------------------------------------------------------------
#define AP2  144                          // 64 fp16 + pad
#define AK2  (64 * AP2)                   // 9216
#define AST2 (2 * AK2)                    // K + V = 18432
#define ATTN_SMEM_BYTES (4 * AST2)        // 3 KV stages + Q = 73728

__global__ __launch_bounds__(256)
void attn_tc()
{
    extern __shared__ char smc[];
    const uint32_t sb0 = smem_u32(smc);
    const uint32_t sbQ = sb0 + 3 * AST2;
    const int tid  = threadIdx.x;
    const int wid  = tid >> 5;
    const int lane = tid & 31;
    const int lr = lane & 7, sub = lane >> 3;

    const int qt = (int)gridDim.x - 1 - (int)blockIdx.x;   // longest first
    const int bh = blockIdx.y;
    const int b  = bh >> 4, h = bh & 15;
    const size_t planeT = (size_t)bh * Tv * 64;   // [t][d] arrays
    const int q0 = qt * 128;
    const int ktmax = 2 * qt + 1;                 // >= 1 always

    auto stage_kv = [&](int k0n, uint32_t sb) {
        #pragma unroll
        for (int i = 0; i < 4; ++i) {
            const int f = tid + (i << 8);
            const int ten = f >> 9;               // 0:K 1:V  (both [t][d])
            const int g = f & 511;
            const int row = g >> 3, cb = (g & 7) << 4;
            const unsigned short* src = (ten ? gv16 : gk16)
                + planeT + (size_t)(k0n + row) * 64 + (cb >> 1);
            cp16(sb + ten * AK2 + row * AP2 + cb, src);
        }
        cp_commit();
    };

    // --- prologue: Q -> sbQ; kv(0) -> stage0; kv(1) -> stage1
    #pragma unroll
    for (int i = 0; i < 4; ++i) {
        const int f = tid + (i << 8);             // 0..1023
        const int row = f >> 3, cb = (f & 7) << 4;
        cp16(sbQ + row * AP2 + cb,
             gq16 + planeT + (size_t)(q0 + row) * 64 + (cb >> 1));
    }
    cp_commit();
    stage_kv(0, sb0);
    stage_kv(64, sb0 + AST2);
    cp_wait<2>();        // Q group complete
    __syncthreads();

    // Q fragments -> registers (reused across all k-tiles)
    uint32_t qh[4][4];
    {
        const uint32_t aQ = (uint32_t)((wid * 16 + (sub & 1) * 8 + lr) * AP2
                                       + (sub >> 1) * 16);
        #pragma unroll
        for (int kk = 0; kk < 4; ++kk)
            ldsm_x4(sbQ + aQ + kk * 32,
                    qh[kk][0], qh[kk][1], qh[kk][2], qh[kk][3]);
    }

    float o[8][4] = {};
    float dl[4] = {};                       // l accumulator (ones-MMA)
    const uint32_t ones2[2] = {0x3C003C00u, 0x3C003C00u};   // (1.0h,1.0h) x2
    const int r  = lane >> 2, cq = (lane & 3) << 1;
    const int qg0 = q0 + wid * 16 + r, qg1 = qg0 + 8;
    const int qlo = q0 + wid * 16;         // warp's MINIMUM row (mask gate)
    // K (non-trans): rows are keys (n), cols d (k)
    const uint32_t bO = (uint32_t)(((sub >> 1) * 8 + lr) * AP2 + (sub & 1) * 16);
    // V (trans): rows are keys (k), cols d (n)
    const uint32_t vO = (uint32_t)(((sub & 1) * 8 + lr) * AP2 + ((sub >> 1) * 8) * 2);

    #pragma unroll 1
    for (int kt = 0; kt <= ktmax; ++kt) {
        if (kt < ktmax) cp_wait<1>(); else cp_wait<0>();
        __syncthreads();
        if (kt + 2 <= ktmax)
            stage_kv((kt + 2) << 6, sb0 + (uint32_t)((kt + 2) % 3) * AST2);

        const uint32_t sb = sb0 + (uint32_t)(kt % 3) * AST2;
        const uint32_t Kh = sb, Vh = sb + AK2;
        const int k0 = kt << 6;

        // ---- S = Q K^T (scale pre-folded into q)
        float s[8][4] = {};
        #pragma unroll
        for (int kk = 0; kk < 4; ++kk) {
            uint32_t bhF[8][2];
            #pragma unroll
            for (int p = 0; p < 4; ++p) {
                const uint32_t off = bO + (uint32_t)(p * 16 * AP2) + kk * 32;
                uint32_t x0, x1, x2, x3;
                ldsm_x4(Kh + off, x0, x1, x2, x3);
                bhF[2*p][0] = x0;     bhF[2*p][1] = x1;
                bhF[2*p+1][0] = x2;   bhF[2*p+1][1] = x3;
            }
            #pragma unroll
            for (int nt = 0; nt < 8; ++nt)
                mma16816(s[nt], qh[kk], bhF[nt]);
        }

        // ---- causal mask: gate on warp's minimum row
        if (k0 + 63 > qlo) {
            #pragma unroll
            for (int nt = 0; nt < 8; ++nt) {
                const int kg = k0 + 8 * nt + cq;
                if (kg     > qg0) s[nt][0] = -CUDART_INF_F;
                if (kg + 1 > qg0) s[nt][1] = -CUDART_INF_F;
                if (kg     > qg1) s[nt][2] = -CUDART_INF_F;
                if (kg + 1 > qg1) s[nt][3] = -CUDART_INF_F;
            }
        }

        // ---- P = 2^s, packed fp16 (accumulator layout == A-operand layout)
        uint32_t ph[4][4];
        #pragma unroll
        for (int kk = 0; kk < 4; ++kk) {
            ph[kk][0] = pack_h2(ex2f(s[2*kk][0]),   ex2f(s[2*kk][1]));
            ph[kk][1] = pack_h2(ex2f(s[2*kk][2]),   ex2f(s[2*kk][3]));
            ph[kk][2] = pack_h2(ex2f(s[2*kk+1][0]), ex2f(s[2*kk+1][1]));
            ph[kk][3] = pack_h2(ex2f(s[2*kk+1][2]), ex2f(s[2*kk+1][3]));
        }

        // ---- l += P @ ones (row sums, fp32 accumulate, cross-tile)
        #pragma unroll
        for (int kk = 0; kk < 4; ++kk)
            mma16816(dl, ph[kk], ones2);

        // ---- O += P @ V  (V [t][d] rows=k; trans ldmatrix -> B fragments)
        #pragma unroll
        for (int kk = 0; kk < 4; ++kk) {
            uint32_t vhF[8][2];
            #pragma unroll
            for (int p = 0; p < 4; ++p) {
                const uint32_t off = vO + (uint32_t)(kk * 16 * AP2) + p * 32;
                uint32_t x0, x1, x2, x3;
                ldsm_x4_t(Vh + off, x0, x1, x2, x3);
                vhF[2*p][0] = x0;     vhF[2*p][1] = x1;
                vhF[2*p+1][0] = x2;   vhF[2*p+1][1] = x3;
            }
            #pragma unroll
            for (int nt = 0; nt < 8; ++nt)
                mma16816(o[nt], ph[kk], vhF[nt]);
        }
    }

    // ---- epilogue: normalize by l, write gatt16 fp16 [B,T,C]
    const float i0 = 1.0f / dl[0], i1 = 1.0f / dl[2];
    const int t0r = q0 + wid * 16 + r, t1r = t0r + 8;
    #pragma unroll
    for (int nt = 0; nt < 8; ++nt) {
        const int col = h * 64 + 8 * nt + cq;
        const size_t off0 = ((size_t)(b * Tv + t0r)) * Cv + col;
        const size_t off1 = ((size_t)(b * Tv + t1r)) * Cv + col;
        *(uint32_t*)(gatt16 + off0) = pack_h2(o[nt][0] * i0, o[nt][1] * i0);
        *(uint32_t*)(gatt16 + off1) = pack_h2(o[nt][2] * i1, o[nt][3] * i1);
    }
}

// ---------------------------------------------------------------------------
extern "C" void kernel_launch(void* const* d_in, const int* in_sizes, int n_in,
                              void* d_out, int out_size)
{
    const float* x      = (const float*)d_in[0];   // [B,T,C]
    const float* w_qkv  = (const float*)d_in[1];   // [C, 3C]
    const float* w_proj = (const float*)d_in[2];   // [C, C]
    float* out = (float*)d_out;                    // [B,T,C]

    cudaFuncSetAttribute(mma_gemm<0>,
                         cudaFuncAttributeMaxDynamicSharedMemorySize,
                         GEMM_SMEM_BYTES);
    cudaFuncSetAttribute(mma_gemm<1>,
                         cudaFuncAttributeMaxDynamicSharedMemorySize,
                         GEMM_SMEM_BYTES);
    cudaFuncSetAttribute(attn_tc,
                         cudaFuncAttributeMaxDynamicSharedMemorySize,
                         ATTN_SMEM_BYTES);
    cudaFuncSetAttribute(mma_gemm<0>,
                         cudaFuncAttributePreferredSharedMemoryCarveout, 100);
    cudaFuncSetAttribute(mma_gemm<1>,
                         cudaFuncAttributePreferredSharedMemoryCarveout, 100);
    cudaFuncSetAttribute(attn_tc,
                         cudaFuncAttributePreferredSharedMemoryCarveout, 100);

    const dim3 blk(256);

    // 0) fp16 conversions of x and weights
    convert_x<<<NTOK * Cv / 4 / 256, blk>>>(x);
    transpose_h<<<dim3(C3 / 32, Cv / 32), dim3(32, 8)>>>(w_qkv, 0);
    transpose_h<<<dim3(Cv / 32, Cv / 32), dim3(32, 8)>>>(w_proj, 1);

    // 1) QKV GEMM (persistent) -> gq16 (pre-scaled) / gk16 / gv16 [t][d]
    mma_gemm<0><<<GEMM_GRID, blk, GEMM_SMEM_BYTES>>>(nullptr);

    // 2) fp16 tensor-core causal flash attention -> gatt16
    attn_tc<<<dim3(Tv / 128, Bv * Hv), blk, ATTN_SMEM_BYTES>>>();

    // 3) proj GEMM (persistent) -> out (fp32)
    mma_gemm<1><<<GEMM_GRID, blk, GEMM_SMEM_BYTES>>>(out);
}

// round 17
// speedup vs baseline: 1.0230x; 1.0230x over previous
#include <cuda_runtime.h>
#include <cuda_fp16.h>
#include <math_constants.h>
#include <cstdint>

// Problem constants
#define Bv   4
#define Tv   2048
#define Cv   1024
#define Hv   16
#define HDv  64
#define NTOK (Bv * Tv)      // 8192
#define C3   (3 * Cv)       // 3072

// ---- Scratch (static device globals -- allocation-guard safe) -------------
__device__ __align__(16) unsigned short gx16[(size_t)NTOK * Cv];      // x [M,K]
__device__ __align__(16) unsigned short gatt16[(size_t)NTOK * Cv];    // att [M,K]
__device__ __align__(16) unsigned short gw1t16[(size_t)C3 * Cv];      // w_qkv^T [N,K]
__device__ __align__(16) unsigned short gw2t16[(size_t)Cv * Cv];      // w_proj^T [N,K]
__device__ __align__(16) unsigned short gq16[(size_t)Bv * Hv * Tv * HDv];  // [bh][t][d] (pre-scaled)
__device__ __align__(16) unsigned short gk16[(size_t)Bv * Hv * Tv * HDv];  // [bh][t][d]
__device__ __align__(16) unsigned short gv16[(size_t)Bv * Hv * Tv * HDv];  // [bh][t][d]

// scale folded into q: 1/sqrt(64) * log2(e)
#define QSCALE 0.1803368801111204f

// ---- portable tensor-core helpers (sm_80+ PTX, compiles at compute_103) ---
__device__ __forceinline__ uint32_t smem_u32(const void* p) {
    uint32_t a;
    asm("{ .reg .u64 t; cvta.to.shared.u64 t, %1; cvt.u32.u64 %0, t; }"
        : "=r"(a) : "l"(p));
    return a;
}
__device__ __forceinline__ void ldsm_x4(uint32_t a, uint32_t& r0, uint32_t& r1,
                                        uint32_t& r2, uint32_t& r3) {
    asm volatile("ldmatrix.sync.aligned.m8n8.x4.shared.b16 {%0,%1,%2,%3}, [%4];"
                 : "=r"(r0), "=r"(r1), "=r"(r2), "=r"(r3) : "r"(a));
}
__device__ __forceinline__ void ldsm_x4_t(uint32_t a, uint32_t& r0, uint32_t& r1,
                                          uint32_t& r2, uint32_t& r3) {
    asm volatile("ldmatrix.sync.aligned.m8n8.x4.trans.shared.b16 {%0,%1,%2,%3}, [%4];"
                 : "=r"(r0), "=r"(r1), "=r"(r2), "=r"(r3) : "r"(a));
}
__device__ __forceinline__ void mma16816(float* d, const uint32_t* a, const uint32_t* b) {
    asm volatile("mma.sync.aligned.m16n8k16.row.col.f32.f16.f16.f32 "
                 "{%0,%1,%2,%3}, {%4,%5,%6,%7}, {%8,%9}, {%0,%1,%2,%3};"
                 : "+f"(d[0]), "+f"(d[1]), "+f"(d[2]), "+f"(d[3])
                 : "r"(a[0]), "r"(a[1]), "r"(a[2]), "r"(a[3]),
                   "r"(b[0]), "r"(b[1]));
}
__device__ __forceinline__ void cp16(uint32_t s, const unsigned short* g) {
    asm volatile("cp.async.cg.shared.global [%0], [%1], 16;"
                 :: "r"(s), "l"(__cvta_generic_to_global(g)) : "memory");
}
__device__ __forceinline__ void cp_commit() {
    asm volatile("cp.async.commit_group;" ::: "memory");
}
template <int N> __device__ __forceinline__ void cp_wait() {
    asm volatile("cp.async.wait_group %0;" :: "n"(N) : "memory");
}
// pack two fp32 into fp16x2: a -> low half, b -> high half (RN)
__device__ __forceinline__ uint32_t pack_h2(float a, float b) {
    uint32_t r;
    asm("cvt.rn.f16x2.f32 %0, %2, %1;" : "=r"(r) : "f"(a), "f"(b));
    return r;
}
__device__ __forceinline__ float ex2f(float x) {
    float r; asm("ex2.approx.f32 %0, %1;" : "=f"(r) : "f"(x)); return r;
}

// ---------------------------------------------------------------------------
// Merged conversion kernel (one launch):
//   blocks [0, 8192)            : x fp32 -> gx16
//   blocks [8192, 8192+3072)    : w_qkv [K,N=3072] -> gw1t16 [N,K]
//   blocks [11264, 11264+1024)  : w_proj [K,N=1024] -> gw2t16 [N,K]
// ---------------------------------------------------------------------------
#define CVT_XBLKS  (NTOK * Cv / 4 / 256)     // 8192
#define CVT_W1BLKS ((C3 / 32) * (Cv / 32))   // 3072
#define CVT_W2BLKS ((Cv / 32) * (Cv / 32))   // 1024

__global__ __launch_bounds__(256)
void convert_all(const float* __restrict__ xin,
                 const float* __restrict__ w1,
                 const float* __restrict__ w2)
{
    const int bx  = blockIdx.x;
    const int tid = threadIdx.x;

    if (bx < CVT_XBLKS) {
        const size_t i = (size_t)bx * 256 + tid;   // float4 index
        const float4 v = ((const float4*)xin)[i];
        uint2 o;
        o.x = pack_h2(v.x, v.y);
        o.y = pack_h2(v.z, v.w);
        ((uint2*)gx16)[i] = o;
        return;
    }

    // transpose+convert path
    const int mode = (bx < CVT_XBLKS + CVT_W1BLKS) ? 0 : 1;
    const int b2 = mode == 0 ? bx - CVT_XBLKS : bx - CVT_XBLKS - CVT_W1BLKS;
    const int NBX = mode == 0 ? (C3 / 32) : (Cv / 32);
    const int bxx = b2 % NBX;
    const int byy = b2 / NBX;
    const int N = mode == 0 ? C3 : Cv;
    const float* in = mode == 0 ? w1 : w2;
    unsigned short* dst = mode == 0 ? gw1t16 : gw2t16;

    __shared__ float t[32][33];
    const int tx = tid & 31, ty = tid >> 5;
    const int x  = bxx * 32 + tx;            // N index (read)
    const int y0 = byy * 32;                 // K base
    #pragma unroll
    for (int j = 0; j < 4; ++j)
        t[ty + 8 * j][tx] = in[(size_t)(y0 + ty + 8 * j) * N + x];
    __syncthreads();
    const int ox  = y0 + tx;                 // K index (write)
    const int oy0 = bxx * 32;                // N base (write)
    #pragma unroll
    for (int j = 0; j < 4; ++j) {
        const float v = t[tx][ty + 8 * j];
        dst[(size_t)(oy0 + ty + 8 * j) * Cv + ox] =
            __half_as_ushort(__float2half_rn(v));
    }
}

// ---------------------------------------------------------------------------
// fp16 tensor-core GEMM via mma.sync: C[M,N] = A[M,1024] @ B[N,1024]^T,
// fp32 reg accumulators. 128x128 tile, BK=64, 8 warps (4M x 2N).
// 3-stage cp.async pipeline, single __syncthreads per chunk (R15 structure —
// measured best; kernel is at the mma.sync HMMA issue-rate ceiling).
// MODE 0: A=gx16,  B=gw1t16, scatter fp16 into gq16 (scaled)/gk16/gv16 [t][d]
// MODE 1: A=gatt16, B=gw2t16, write Cout fp32 row-major (N=1024)
// ---------------------------------------------------------------------------
#define TP2     144                        // 64 fp16 = 128B + 16 pad
#define TB2     (128 * TP2)                // 18432 per tensor tile
#define STAGE2  (2 * TB2)                  // A + B = 36864
#define GEMM_SMEM_BYTES (3 * STAGE2)       // 110592

template <int MODE>
__global__ __launch_bounds__(256)
void mma_gemm(float* __restrict__ Cout)
{
    extern __shared__ char smem[];
    const uint32_t sbase = smem_u32(smem);

    const int tid  = threadIdx.x;
    const int lane = tid & 31;
    const int wid  = tid >> 5;
    const int wm   = wid & 3;
    const int wn   = wid >> 2;
    const int m0   = blockIdx.y * 128;
    const int n0   = blockIdx.x * 128;

    const unsigned short* A16 = (MODE == 0) ? gx16   : gatt16;
    const unsigned short* B16 = (MODE == 0) ? gw1t16 : gw2t16;

    const int lr  = lane & 7;
    const int sub = lane >> 3;
    const uint32_t aOff = (uint32_t)((wm * 32 + (sub & 1) * 8 + lr) * TP2
                                     + (sub >> 1) * 16);
    const uint32_t bOff = (uint32_t)((wn * 64 + (sub >> 1) * 8 + lr) * TP2
                                     + (sub & 1) * 16);

    float d[2][8][4] = {};

    auto stage_chunk = [&](int kc, uint32_t sb) {
        #pragma unroll
        for (int i = 0; i < 8; ++i) {
            const int f   = tid + (i << 8);
            const int ten = f >> 10;               // 0:A 1:B
            const int g   = f & 1023;
            const int row = g >> 3, cb = (g & 7) << 4;
            const unsigned short* src = (ten ? B16 + (size_t)(n0 + row) * Cv
                                             : A16 + (size_t)(m0 + row) * Cv)
                                        + kc + (cb >> 1);
            cp16(sb + (uint32_t)ten * TB2 + row * TP2 + cb, src);
        }
        cp_commit();
    };

    stage_chunk(0, sbase);
    stage_chunk(64, sbase + STAGE2);

    #pragma unroll 1
    for (int chunk = 0; chunk < 16; ++chunk) {
        if (chunk + 1 < 16) cp_wait<1>(); else cp_wait<0>();
        __syncthreads();
        if (chunk + 2 < 16)
            stage_chunk((chunk + 2) << 6,
                        sbase + (uint32_t)((chunk + 2) % 3) * STAGE2);

        const uint32_t sb = sbase + (uint32_t)(chunk % 3) * STAGE2;
        #pragma unroll
        for (int ks = 0; ks < 4; ++ks) {
            const uint32_t ko = ks * 32;
            uint32_t a[2][4];
            #pragma unroll
            for (int mt = 0; mt < 2; ++mt)
                ldsm_x4(sb + aOff + mt * (16 * TP2) + ko,
                        a[mt][0], a[mt][1], a[mt][2], a[mt][3]);
            uint32_t bF[8][2];
            #pragma unroll
            for (int p = 0; p < 4; ++p) {
                uint32_t x0, x1, x2, x3;
                ldsm_x4(sb + TB2 + bOff + p * (16 * TP2) + ko, x0, x1, x2, x3);
                bF[2 * p][0] = x0;     bF[2 * p][1] = x1;
                bF[2 * p + 1][0] = x2; bF[2 * p + 1][1] = x3;
            }
            #pragma unroll
            for (int mt = 0; mt < 2; ++mt)
                #pragma unroll
                for (int nt = 0; nt < 8; ++nt)
                    mma16816(d[mt][nt], a[mt], bF[nt]);
        }
    }

    // Epilogue
    #pragma unroll
    for (int mt = 0; mt < 2; ++mt) {
        const int mA = m0 + wm * 32 + mt * 16 + (lane >> 2);
        if (MODE == 0) {
            const int bb = mA >> 11;
            const int tt = mA & 2047;
            const int t2 = (mA + 8) & 2047;   // same batch (128 | 2048)
            #pragma unroll
            for (int nt = 0; nt < 8; ++nt) {
                const int ncol = n0 + wn * 64 + nt * 8 + (lane & 3) * 2;
                const int sec = ncol >> 10;              // 0:q 1:k 2:v
                const int hh  = (ncol & 1023) >> 6;
                const int dd  = ncol & 63;
                const float qs = (sec == 0) ? QSCALE : 1.0f;
                const uint32_t p0 = pack_h2(d[mt][nt][0] * qs, d[mt][nt][1] * qs);
                const uint32_t p1 = pack_h2(d[mt][nt][2] * qs, d[mt][nt][3] * qs);
                unsigned short* dh = (sec == 0) ? gq16
                                   : (sec == 1) ? gk16 : gv16;
                const size_t base = (size_t)(bb * Hv + hh) * Tv;
                *(uint32_t*)(dh + (base + tt) * 64 + dd) = p0;
                *(uint32_t*)(dh + (base + t2) * 64 + dd) = p1;
            }
        } else {
            #pragma unroll
            for (int nt = 0; nt < 8; ++nt) {
                const int ncol = n0 + wn * 64 + nt * 8 + (lane & 3) * 2;
                *(float2*)(Cout + (size_t)mA * Cv + ncol) =
                    make_float2(d[mt][nt][0], d[mt][nt][1]);
                *(float2*)(Cout + (size_t)(mA + 8) * Cv + ncol) =
                    make_float2(d[mt][nt][2], d[mt][nt][3]);
            }
        }
    }
}

// ---------------------------------------------------------------------------
// fp16 tensor-core causal flash attention (mma.sync), bounded-score softmax.
// K and V both [bh][t][d]; V B-fragments via ldmatrix.x4.trans.
// Row-sum l via fp32 adds + quad shfl (fma/alu pipes) -- ones-MMA removed
// to cut 6% off the saturated tensor pipe.
// ---------------------------------------------------------------------------
#define AP2  144                          // 64 fp16 + pad
#define AK2  (64 * AP2)                   // 9216
#define AST2 (2 * AK2)                    // K + V = 18432
#define ATTN_SMEM_BYTES (4 * AST2)        // 3 KV stages + Q = 73728

__global__ __launch_bounds__(256)
void attn_tc()
{
    extern __shared__ char smc[];
    const uint32_t sb0 = smem_u32(smc);
    const uint32_t sbQ = sb0 + 3 * AST2;
    const int tid  = threadIdx.x;
    const int wid  = tid >> 5;
    const int lane = tid & 31;
    const int lr = lane & 7, sub = lane >> 3;

    const int qt = (int)gridDim.x - 1 - (int)blockIdx.x;   // longest first
    const int bh = blockIdx.y;
    const int b  = bh >> 4, h = bh & 15;
    const size_t planeT = (size_t)bh * Tv * 64;   // [t][d] arrays
    const int q0 = qt * 128;
    const int ktmax = 2 * qt + 1;                 // >= 1 always

    auto stage_kv = [&](int k0n, uint32_t sb) {
        #pragma unroll
        for (int i = 0; i < 4; ++i) {
            const int f = tid + (i << 8);
            const int ten = f >> 9;               // 0:K 1:V  (both [t][d])
            const int g = f & 511;
            const int row = g >> 3, cb = (g & 7) << 4;
            const unsigned short* src = (ten ? gv16 : gk16)
                + planeT + (size_t)(k0n + row) * 64 + (cb >> 1);
            cp16(sb + ten * AK2 + row * AP2 + cb, src);
        }
        cp_commit();
    };

    // --- prologue: Q -> sbQ; kv(0) -> stage0; kv(1) -> stage1
    #pragma unroll
    for (int i = 0; i < 4; ++i) {
        const int f = tid + (i << 8);             // 0..1023
        const int row = f >> 3, cb = (f & 7) << 4;
        cp16(sbQ + row * AP2 + cb,
             gq16 + planeT + (size_t)(q0 + row) * 64 + (cb >> 1));
    }
    cp_commit();
    stage_kv(0, sb0);
    stage_kv(64, sb0 + AST2);
    cp_wait<2>();        // Q group complete
    __syncthreads();

    // Q fragments -> registers (reused across all k-tiles)
    uint32_t qh[4][4];
    {
        const uint32_t aQ = (uint32_t)((wid * 16 + (sub & 1) * 8 + lr) * AP2
                                       + (sub >> 1) * 16);
        #pragma unroll
        for (int kk = 0; kk < 4; ++kk)
            ldsm_x4(sbQ + aQ + kk * 32,
                    qh[kk][0], qh[kk][1], qh[kk][2], qh[kk][3]);
    }

    float o[8][4] = {};
    float l0 = 0.f, l1 = 0.f;              // row-sum accumulators (fp32)
    const int r  = lane >> 2, cq = (lane & 3) << 1;
    const int qg0 = q0 + wid * 16 + r, qg1 = qg0 + 8;
    const int qlo = q0 + wid * 16;         // warp's MINIMUM row (mask gate)
    // K (non-trans): rows are keys (n), cols d (k)
    const uint32_t bO = (uint32_t)(((sub >> 1) * 8 + lr) * AP2 + (sub & 1) * 16);
    // V (trans): rows are keys (k), cols d (n)
    const uint32_t vO = (uint32_t)(((sub & 1) * 8 + lr) * AP2 + ((sub >> 1) * 8) * 2);

    #pragma unroll 1
    for (int kt = 0; kt <= ktmax; ++kt) {
        if (kt < ktmax) cp_wait<1>(); else cp_wait<0>();
        __syncthreads();
        if (kt + 2 <= ktmax)
            stage_kv((kt + 2) << 6, sb0 + (uint32_t)((kt + 2) % 3) * AST2);

        const uint32_t sb = sb0 + (uint32_t)(kt % 3) * AST2;
        const uint32_t Kh = sb, Vh = sb + AK2;
        const int k0 = kt << 6;

        // ---- S = Q K^T (scale pre-folded into q)
        float s[8][4] = {};
        #pragma unroll
        for (int kk = 0; kk < 4; ++kk) {
            uint32_t bhF[8][2];
            #pragma unroll
            for (int p = 0; p < 4; ++p) {
                const uint32_t off = bO + (uint32_t)(p * 16 * AP2) + kk * 32;
                uint32_t x0, x1, x2, x3;
                ldsm_x4(Kh + off, x0, x1, x2, x3);
                bhF[2*p][0] = x0;     bhF[2*p][1] = x1;
                bhF[2*p+1][0] = x2;   bhF[2*p+1][1] = x3;
            }
            #pragma unroll
            for (int nt = 0; nt < 8; ++nt)
                mma16816(s[nt], qh[kk], bhF[nt]);
        }

        // ---- causal mask: gate on warp's minimum row
        if (k0 + 63 > qlo) {
            #pragma unroll
            for (int nt = 0; nt < 8; ++nt) {
                const int kg = k0 + 8 * nt + cq;
                if (kg     > qg0) s[nt][0] = -CUDART_INF_F;
                if (kg + 1 > qg0) s[nt][1] = -CUDART_INF_F;
                if (kg     > qg1) s[nt][2] = -CUDART_INF_F;
                if (kg + 1 > qg1) s[nt][3] = -CUDART_INF_F;
            }
        }

        // ---- P = 2^s (fp32), row sums on fma pipe, pack to fp16
        uint32_t ph[4][4];
        float sm0 = 0.f, sm1 = 0.f;
        #pragma unroll
        for (int nt = 0; nt < 8; ++nt) {
            const float e0 = ex2f(s[nt][0]);
            const float e1 = ex2f(s[nt][1]);
            const float e2 = ex2f(s[nt][2]);
            const float e3 = ex2f(s[nt][3]);
            sm0 += e0 + e1;
            sm1 += e2 + e3;
            s[nt][0] = e0; s[nt][1] = e1; s[nt][2] = e2; s[nt][3] = e3;
        }
        sm0 += __shfl_xor_sync(0xffffffffu, sm0, 1);
        sm0 += __shfl_xor_sync(0xffffffffu, sm0, 2);
        sm1 += __shfl_xor_sync(0xffffffffu, sm1, 1);
        sm1 += __shfl_xor_sync(0xffffffffu, sm1, 2);
        l0 += sm0;
        l1 += sm1;
        #pragma unroll
        for (int kk = 0; kk < 4; ++kk) {
            ph[kk][0] = pack_h2(s[2*kk][0],   s[2*kk][1]);
            ph[kk][1] = pack_h2(s[2*kk][2],   s[2*kk][3]);
            ph[kk][2] = pack_h2(s[2*kk+1][0], s[2*kk+1][1]);
            ph[kk][3] = pack_h2(s[2*kk+1][2], s[2*kk+1][3]);
        }

        // ---- O += P @ V  (V [t][d] rows=k; trans ldmatrix -> B fragments)
        #pragma unroll
        for (int kk = 0; kk < 4; ++kk) {
            uint32_t vhF[8][2];
            #pragma unroll
            for (int p = 0; p < 4; ++p) {
                const uint32_t off = vO + (uint32_t)(kk * 16 * AP2) + p * 32;
                uint32_t x0, x1, x2, x3;
                ldsm_x4_t(Vh + off, x0, x1, x2, x3);
                vhF[2*p][0] = x0;     vhF[2*p][1] = x1;
                vhF[2*p+1][0] = x2;   vhF[2*p+1][1] = x3;
            }
            #pragma unroll
            for (int nt = 0; nt < 8; ++nt)
                mma16816(o[nt], ph[kk], vhF[nt]);
        }
    }

    // ---- epilogue: normalize by l, write gatt16 fp16 [B,T,C]
    const float i0 = 1.0f / l0, i1 = 1.0f / l1;
    const int t0r = q0 + wid * 16 + r, t1r = t0r + 8;
    #pragma unroll
    for (int nt = 0; nt < 8; ++nt) {
        const int col = h * 64 + 8 * nt + cq;
        const size_t off0 = ((size_t)(b * Tv + t0r)) * Cv + col;
        const size_t off1 = ((size_t)(b * Tv + t1r)) * Cv + col;
        *(uint32_t*)(gatt16 + off0) = pack_h2(o[nt][0] * i0, o[nt][1] * i0);
        *(uint32_t*)(gatt16 + off1) = pack_h2(o[nt][2] * i1, o[nt][3] * i1);
    }
}

// ---------------------------------------------------------------------------
extern "C" void kernel_launch(void* const* d_in, const int* in_sizes, int n_in,
                              void* d_out, int out_size)
{
    const float* x      = (const float*)d_in[0];   // [B,T,C]
    const float* w_qkv  = (const float*)d_in[1];   // [C, 3C]
    const float* w_proj = (const float*)d_in[2];   // [C, C]
    float* out = (float*)d_out;                    // [B,T,C]

    cudaFuncSetAttribute(mma_gemm<0>,
                         cudaFuncAttributeMaxDynamicSharedMemorySize,
                         GEMM_SMEM_BYTES);
    cudaFuncSetAttribute(mma_gemm<1>,
                         cudaFuncAttributeMaxDynamicSharedMemorySize,
                         GEMM_SMEM_BYTES);
    cudaFuncSetAttribute(attn_tc,
                         cudaFuncAttributeMaxDynamicSharedMemorySize,
                         ATTN_SMEM_BYTES);

    const dim3 blk(256);

    // 0) merged fp16 conversions (x + both weight transposes, one launch)
    convert_all<<<CVT_XBLKS + CVT_W1BLKS + CVT_W2BLKS, blk>>>(x, w_qkv, w_proj);

    // 1) QKV GEMM -> gq16 (pre-scaled) / gk16 / gv16 [t][d]
    mma_gemm<0><<<dim3(C3 / 128, NTOK / 128), blk, GEMM_SMEM_BYTES>>>(nullptr);

    // 2) fp16 tensor-core causal flash attention -> gatt16
    attn_tc<<<dim3(Tv / 128, Bv * Hv), blk, ATTN_SMEM_BYTES>>>();

    // 3) proj GEMM -> out (fp32)
    mma_gemm<1><<<dim3(Cv / 128, NTOK / 128), blk, GEMM_SMEM_BYTES>>>(out);
}